// round 14
// baseline (speedup 1.0000x reference)
#include <cuda_runtime.h>

// Depthwise 3x3 conv with one-hot (hard-softmax) weight == pure spatial shift:
//   out[b,c,h,w] = x[b,c,h+dh,w+dw]  (zero outside), (dh,dw) = abs-argmax of
// the 9 weights (first max wins, matching jnp.argmax).
// Shapes fixed: B=16, C=64, H=256, W=256 fp32.
//
// Converged memory configuration (~6.45 TB/s combined R+W):
//  - 2 warp-interleaved float4 streams per thread (MLP=2)
//  - dw=+-1 path: 4x LDG.32 at 16B lane stride
//  - plain stores, flat grid
// Block-size trend: 256->512 threads gave kernel 76.0->74.6us (fewer
// prologue/scheduling events). R14: 512 -> 1024 threads (8192 blocks;
// 22 regs/8B smem -> still 2 blocks = 2048 threads per SM).

#define H_DIM 256
#define W_DIM 256

__device__ __forceinline__ float4
load_shifted(const float* __restrict__ x, int v, int dh, int dw) {
    // v = float4 output index. W=256 -> 64 float4/row.
    const int w4 = v & 63;
    const int h  = (v >> 6) & 255;
    const int bc = v >> 14;

    float4 val = make_float4(0.f, 0.f, 0.f, 0.f);
    const int hi = h + dh;
    if ((unsigned)hi < (unsigned)H_DIM) {
        const float* __restrict__ row = x + ((long long)bc * H_DIM + hi) * W_DIM;
        if (dw == 0) {
            val = __ldg(reinterpret_cast<const float4*>(row) + w4);
        } else {
            // Lane addresses stride 16B across the warp -> well coalesced.
            const int wa = (w4 << 2) + dw;
            val.x = ((unsigned)wa       < (unsigned)W_DIM) ? __ldg(row + wa)     : 0.f;
            val.y = ((unsigned)(wa + 1) < (unsigned)W_DIM) ? __ldg(row + wa + 1) : 0.f;
            val.z = ((unsigned)(wa + 2) < (unsigned)W_DIM) ? __ldg(row + wa + 2) : 0.f;
            val.w = ((unsigned)(wa + 3) < (unsigned)W_DIM) ? __ldg(row + wa + 3) : 0.f;
        }
    }
    return val;
}

__global__ void __launch_bounds__(1024)
shift_fused2_b1024_kernel(const float* __restrict__ x,
                          const float* __restrict__ wt,
                          float* __restrict__ out) {
    __shared__ int s_dh, s_dw;
    if (threadIdx.x == 0) {
        float best = -1.0f;
        int bi = 0;
#pragma unroll
        for (int i = 0; i < 9; ++i) {
            float a = fabsf(__ldg(wt + i));
            if (a > best) { best = a; bi = i; }  // strict > : first max wins
        }
        s_dh = bi / 3 - 1;
        s_dw = bi % 3 - 1;
    }
    __syncthreads();
    const int dh = s_dh;
    const int dw = s_dw;

    // Block covers 2048 consecutive float4s; thread t handles t and t+1024.
    const int base = blockIdx.x * 2048;
    const int v0 = base + threadIdx.x;
    const int v1 = v0 + 1024;

    // Two independent load chains (front-batched by the compiler -> MLP 2).
    float4 a = load_shifted(x, v0, dh, dw);
    float4 b = load_shifted(x, v1, dh, dw);

    float4* __restrict__ o4 = reinterpret_cast<float4*>(out);
    o4[v0] = a;
    o4[v1] = b;
}

extern "C" void kernel_launch(void* const* d_in, const int* in_sizes, int n_in,
                              void* d_out, int out_size) {
    const float* x  = (const float*)d_in[0];
    const float* wt = (const float*)d_in[1];
    float* out = (float*)d_out;

    const int n4 = out_size >> 2;          // 16,777,216 float4
    const int blocks = n4 / 2048;          // 8192 blocks, 1024 threads, 2 f4/thread
    shift_fused2_b1024_kernel<<<blocks, 1024>>>(x, wt, out);
}

// round 15
// speedup vs baseline: 1.0127x; 1.0127x over previous
#include <cuda_runtime.h>

// Depthwise 3x3 conv with one-hot (hard-softmax) weight == pure spatial shift:
//   out[b,c,h,w] = x[b,c,h+dh,w+dw]  (zero outside), (dh,dw) = abs-argmax of
// the 9 weights (first max wins, matching jnp.argmax).
// Shapes fixed: B=16, C=64, H=256, W=256 fp32.
//
// FINAL kernel — measured global optimum of the swept design space
// (14 rounds): kernel ~74.6us, 6464 GB/s combined R+W = ~81% of HBM spec,
// the practical GB300 streaming ceiling for a 512MB single-touch copy.
//  - single fused kernel; per-block argmax (9 L2-hit loads + one barrier)
//  - 2 warp-interleaved float4 streams per thread (MLP=2; 1 and 4 are worse)
//  - dw=+-1 path: 4x LDG.32 at 16B lane stride (beats LDG.128+scalar, shuffle)
//  - plain stores/loads (streaming hints neutral-to-negative)
//  - flat grid, 512-thread blocks (256 and 1024 both measured slower)

#define H_DIM 256
#define W_DIM 256

__device__ __forceinline__ float4
load_shifted(const float* __restrict__ x, int v, int dh, int dw) {
    // v = float4 output index. W=256 -> 64 float4/row.
    const int w4 = v & 63;
    const int h  = (v >> 6) & 255;
    const int bc = v >> 14;

    float4 val = make_float4(0.f, 0.f, 0.f, 0.f);
    const int hi = h + dh;
    if ((unsigned)hi < (unsigned)H_DIM) {
        const float* __restrict__ row = x + ((long long)bc * H_DIM + hi) * W_DIM;
        if (dw == 0) {
            val = __ldg(reinterpret_cast<const float4*>(row) + w4);
        } else {
            // Lane addresses stride 16B across the warp -> well coalesced.
            const int wa = (w4 << 2) + dw;
            val.x = ((unsigned)wa       < (unsigned)W_DIM) ? __ldg(row + wa)     : 0.f;
            val.y = ((unsigned)(wa + 1) < (unsigned)W_DIM) ? __ldg(row + wa + 1) : 0.f;
            val.z = ((unsigned)(wa + 2) < (unsigned)W_DIM) ? __ldg(row + wa + 2) : 0.f;
            val.w = ((unsigned)(wa + 3) < (unsigned)W_DIM) ? __ldg(row + wa + 3) : 0.f;
        }
    }
    return val;
}

__global__ void __launch_bounds__(512)
shift_fused2_b512_kernel(const float* __restrict__ x,
                         const float* __restrict__ wt,
                         float* __restrict__ out) {
    __shared__ int s_dh, s_dw;
    if (threadIdx.x == 0) {
        float best = -1.0f;
        int bi = 0;
#pragma unroll
        for (int i = 0; i < 9; ++i) {
            float a = fabsf(__ldg(wt + i));
            if (a > best) { best = a; bi = i; }  // strict > : first max wins
        }
        s_dh = bi / 3 - 1;
        s_dw = bi % 3 - 1;
    }
    __syncthreads();
    const int dh = s_dh;
    const int dw = s_dw;

    // Block covers 1024 consecutive float4s; thread t handles t and t+512.
    const int base = blockIdx.x * 1024;
    const int v0 = base + threadIdx.x;
    const int v1 = v0 + 512;

    // Two independent load chains (front-batched by the compiler -> MLP 2).
    float4 a = load_shifted(x, v0, dh, dw);
    float4 b = load_shifted(x, v1, dh, dw);

    float4* __restrict__ o4 = reinterpret_cast<float4*>(out);
    o4[v0] = a;
    o4[v1] = b;
}

extern "C" void kernel_launch(void* const* d_in, const int* in_sizes, int n_in,
                              void* d_out, int out_size) {
    const float* x  = (const float*)d_in[0];
    const float* wt = (const float*)d_in[1];
    float* out = (float*)d_out;

    const int n4 = out_size >> 2;          // 16,777,216 float4
    const int blocks = n4 / 1024;          // 16384 blocks, 512 threads, 2 f4/thread
    shift_fused2_b512_kernel<<<blocks, 512>>>(x, wt, out);
}

// round 16
// speedup vs baseline: 1.0131x; 1.0004x over previous
#include <cuda_runtime.h>

// Depthwise 3x3 conv with one-hot (hard-softmax) weight == pure spatial shift:
//   out[b,c,h,w] = x[b,c,h+dh,w+dw]  (zero outside), (dh,dw) = abs-argmax of
// the 9 weights (first max wins, matching jnp.argmax).
// Shapes fixed: B=16, C=64, H=256, W=256 fp32.
//
// FINAL kernel — measured global optimum over 15 rounds of sweeps:
// kernel 74.6-76.1us, ~6.4 TB/s combined R+W = ~80% of HBM spec, at the
// GB300 path-independent LTS/HBM streaming ceiling for a 512MB single-touch
// copy (MLP>2, cache hints, persistent grids, shuffle/vector load
// restructurings, 256/1024-thread blocks all measured neutral or worse).
//  - single fused kernel; per-block argmax (9 L2-hit loads + one barrier)
//  - 2 warp-interleaved float4 streams per thread (MLP=2)
//  - dw=+-1 path: 4x LDG.32 at 16B lane stride
//  - plain loads/stores, flat grid, 512-thread blocks

#define H_DIM 256
#define W_DIM 256

__device__ __forceinline__ float4
load_shifted(const float* __restrict__ x, int v, int dh, int dw) {
    // v = float4 output index. W=256 -> 64 float4/row.
    const int w4 = v & 63;
    const int h  = (v >> 6) & 255;
    const int bc = v >> 14;

    float4 val = make_float4(0.f, 0.f, 0.f, 0.f);
    const int hi = h + dh;
    if ((unsigned)hi < (unsigned)H_DIM) {
        const float* __restrict__ row = x + ((long long)bc * H_DIM + hi) * W_DIM;
        if (dw == 0) {
            val = __ldg(reinterpret_cast<const float4*>(row) + w4);
        } else {
            // Lane addresses stride 16B across the warp -> well coalesced.
            const int wa = (w4 << 2) + dw;
            val.x = ((unsigned)wa       < (unsigned)W_DIM) ? __ldg(row + wa)     : 0.f;
            val.y = ((unsigned)(wa + 1) < (unsigned)W_DIM) ? __ldg(row + wa + 1) : 0.f;
            val.z = ((unsigned)(wa + 2) < (unsigned)W_DIM) ? __ldg(row + wa + 2) : 0.f;
            val.w = ((unsigned)(wa + 3) < (unsigned)W_DIM) ? __ldg(row + wa + 3) : 0.f;
        }
    }
    return val;
}

__global__ void __launch_bounds__(512)
shift_fused2_b512_kernel(const float* __restrict__ x,
                         const float* __restrict__ wt,
                         float* __restrict__ out) {
    __shared__ int s_dh, s_dw;
    if (threadIdx.x == 0) {
        float best = -1.0f;
        int bi = 0;
#pragma unroll
        for (int i = 0; i < 9; ++i) {
            float a = fabsf(__ldg(wt + i));
            if (a > best) { best = a; bi = i; }  // strict > : first max wins
        }
        s_dh = bi / 3 - 1;
        s_dw = bi % 3 - 1;
    }
    __syncthreads();
    const int dh = s_dh;
    const int dw = s_dw;

    // Block covers 1024 consecutive float4s; thread t handles t and t+512.
    const int base = blockIdx.x * 1024;
    const int v0 = base + threadIdx.x;
    const int v1 = v0 + 512;

    // Two independent load chains (front-batched by the compiler -> MLP 2).
    float4 a = load_shifted(x, v0, dh, dw);
    float4 b = load_shifted(x, v1, dh, dw);

    float4* __restrict__ o4 = reinterpret_cast<float4*>(out);
    o4[v0] = a;
    o4[v1] = b;
}

extern "C" void kernel_launch(void* const* d_in, const int* in_sizes, int n_in,
                              void* d_out, int out_size) {
    const float* x  = (const float*)d_in[0];
    const float* wt = (const float*)d_in[1];
    float* out = (float*)d_out;

    const int n4 = out_size >> 2;          // 16,777,216 float4
    const int blocks = n4 / 1024;          // 16384 blocks, 512 threads, 2 f4/thread
    shift_fused2_b512_kernel<<<blocks, 512>>>(x, wt, out);
}